// round 1
// baseline (speedup 1.0000x reference)
#include <cuda_runtime.h>
#include <cuda_bf16.h>
#include <math.h>

// Problem constants
#define Bb 2
#define LL 2048
#define DD 256
#define KK 32
#define FF 64          // 2*K feature dim
#define MM (Bb*LL)     // 4096 rows
#define CC 128         // chunk size
#define NC (LL/CC)     // 16 chunks per batch
#define PI_F 3.14159265358979323846f

// ---------------- scratch (device globals; no allocation allowed) ----------------
__device__ float g_hk[MM*DD];
__device__ float g_hq[MM*DD];
__device__ float g_vc[MM*DD];
__device__ float g_vp[MM*DD];
__device__ float g_g1[MM*64];
__device__ float g_kf[MM*FF];
__device__ float g_qf[MM*FF];
__device__ float g_gates[MM*2];
__device__ float g_S[Bb*NC*FF*DD];       // per-chunk content state sums
__device__ float g_P[Bb*NC*FF*DD];       // exclusive prefix of states
__device__ float g_psum[Bb*NC*2*DD];     // per-chunk pos sums (real, imag)
__device__ float g_pprefix[Bb*NC*2*DD];  // exclusive prefix
__device__ float g_scores[Bb*NC*CC*CC];  // intra-chunk masked scores
__device__ float g_cont[MM*DD];
__device__ float g_norm[MM*DD];

// ================= Kernel 1: fused first-layer GEMMs =================
// out cols: [hk(256, tanh) | hq(256, tanh) | vc(256) | vp(256) | g1(64, relu)]
__global__ __launch_bounds__(256) void k1_gemm(
    const float* __restrict__ x,
    const float* __restrict__ Wk1, const float* __restrict__ bk1,
    const float* __restrict__ Wq1, const float* __restrict__ bq1,
    const float* __restrict__ Wvc, const float* __restrict__ bvc,
    const float* __restrict__ Wvp, const float* __restrict__ bvp,
    const float* __restrict__ Wg1, const float* __restrict__ bg1)
{
    __shared__ float As[16][64];
    __shared__ float Bs[16][64];
    int ct = blockIdx.y;
    const float* W; const float* bias; float* outp; int Nseg; int act; int colbase;
    if (ct < 16) {
        int seg = ct >> 2;
        colbase = (ct & 3) * 64;
        Nseg = 256;
        if (seg == 0)      { W = Wk1; bias = bk1; outp = g_hk; act = 1; }
        else if (seg == 1) { W = Wq1; bias = bq1; outp = g_hq; act = 1; }
        else if (seg == 2) { W = Wvc; bias = bvc; outp = g_vc; act = 0; }
        else               { W = Wvp; bias = bvp; outp = g_vp; act = 0; }
    } else {
        W = Wg1; bias = bg1; outp = g_g1; Nseg = 64; act = 2; colbase = 0;
    }
    int row0 = blockIdx.x * 64;
    int tid = threadIdx.x;
    int ty = tid >> 4, tx = tid & 15;
    int arow = tid >> 2, ak = (tid & 3) * 4;
    int bk = tid >> 4, bc = (tid & 15) * 4;
    float acc[4][4] = {};
    for (int k0 = 0; k0 < 256; k0 += 16) {
        __syncthreads();
        float4 av = *(const float4*)&x[(row0 + arow) * 256 + k0 + ak];
        As[ak+0][arow] = av.x; As[ak+1][arow] = av.y;
        As[ak+2][arow] = av.z; As[ak+3][arow] = av.w;
        float4 bv = *(const float4*)&W[(k0 + bk) * Nseg + colbase + bc];
        *(float4*)&Bs[bk][bc] = bv;
        __syncthreads();
        #pragma unroll
        for (int kk = 0; kk < 16; kk++) {
            float4 a = *(const float4*)&As[kk][ty*4];
            float4 b = *(const float4*)&Bs[kk][tx*4];
            float aa[4] = {a.x, a.y, a.z, a.w};
            float bb[4] = {b.x, b.y, b.z, b.w};
            #pragma unroll
            for (int i = 0; i < 4; i++)
                #pragma unroll
                for (int j = 0; j < 4; j++)
                    acc[i][j] += aa[i] * bb[j];
        }
    }
    #pragma unroll
    for (int i = 0; i < 4; i++) {
        int r = row0 + ty*4 + i;
        #pragma unroll
        for (int j = 0; j < 4; j++) {
            int c = colbase + tx*4 + j;
            float v = acc[i][j] + bias[c];
            if (act == 1) v = tanhf(v);
            else if (act == 2) v = fmaxf(v, 0.f);
            outp[r * Nseg + c] = v;
        }
    }
}

// ================= Kernel 2: phase features + gates =================
__global__ __launch_bounds__(256) void k2_phase(
    const float* __restrict__ Wk2, const float* __restrict__ bk2,
    const float* __restrict__ Wq2, const float* __restrict__ bq2,
    const float* __restrict__ Wg2, const float* __restrict__ bg2)
{
    __shared__ float Ws[256*32];
    __shared__ float rowbuf[8][256];
    __shared__ float Wg2s[128];
    int tid = threadIdx.x;
    int w = tid >> 5, lane = tid & 31;
    int rowbase = blockIdx.x * 32;
    if (tid < 128) Wg2s[tid] = Wg2[tid];

    for (int pass = 0; pass < 2; pass++) {
        const float* Wmat = pass ? Wq2 : Wk2;
        const float* bvec = pass ? bq2 : bk2;
        const float* hsrc = pass ? g_hq : g_hk;
        float* fdst = pass ? g_qf : g_kf;
        __syncthreads();
        for (int i = tid; i < 8192; i += 256) Ws[i] = Wmat[i];
        __syncthreads();
        for (int rr = 0; rr < 4; rr++) {
            int r = rowbase + w * 4 + rr;
            for (int i = lane; i < 256; i += 32) rowbuf[w][i] = hsrc[r*256 + i];
            __syncwarp();
            float s = bvec[lane];
            #pragma unroll 8
            for (int i = 0; i < 256; i++) s += rowbuf[w][i] * Ws[i*32 + lane];
            float ph = tanhf(s) * PI_F;
            float sp, cp; __sincosf(ph, &sp, &cp);
            fdst[r*64 + lane] = cp;
            fdst[r*64 + 32 + lane] = sp;
            __syncwarp();
        }
    }
    // gates
    for (int rr = 0; rr < 4; rr++) {
        int r = rowbase + w*4 + rr;
        float p0 = 0.f, p1 = 0.f;
        for (int i = lane; i < 64; i += 32) {
            float gv = g_g1[r*64 + i];
            p0 += gv * Wg2s[i*2 + 0];
            p1 += gv * Wg2s[i*2 + 1];
        }
        #pragma unroll
        for (int off = 16; off; off >>= 1) {
            p0 += __shfl_xor_sync(~0u, p0, off);
            p1 += __shfl_xor_sync(~0u, p1, off);
        }
        if (lane == 0) {
            float l0 = p0 + bg2[0], l1 = p1 + bg2[1];
            float m = fmaxf(l0, l1);
            float e0 = __expf(l0 - m), e1 = __expf(l1 - m);
            float inv = 1.f / (e0 + e1);
            g_gates[r*2 + 0] = e0 * inv;
            g_gates[r*2 + 1] = e1 * inv;
        }
    }
}

// ================= Kernel 3: per-chunk sums (content state + pos) =================
__global__ __launch_bounds__(256) void k3_chunksum(const float* __restrict__ base_phases)
{
    __shared__ float kfs[8][64];
    int bc = blockIdx.x;            // b*16 + c
    int b = bc >> 4, c = bc & 15;
    int d = threadIdx.x;
    int row0 = b * LL + c * CC;
    float acc[64];
    #pragma unroll
    for (int f = 0; f < 64; f++) acc[f] = 0.f;
    float par = 0.f, pai = 0.f;
    for (int lt0 = 0; lt0 < CC; lt0 += 8) {
        __syncthreads();
        for (int i = d; i < 512; i += 256)
            kfs[i >> 6][i & 63] = g_kf[(row0 + lt0 + (i >> 6)) * 64 + (i & 63)];
        __syncthreads();
        #pragma unroll
        for (int j = 0; j < 8; j++) {
            int r = row0 + lt0 + j;
            float v = g_vc[r * 256 + d];
            #pragma unroll
            for (int f4 = 0; f4 < 16; f4++) {
                float4 kv = *(const float4*)&kfs[j][f4 * 4];
                acc[f4*4+0] += kv.x * v;
                acc[f4*4+1] += kv.y * v;
                acc[f4*4+2] += kv.z * v;
                acc[f4*4+3] += kv.w * v;
            }
            int l = c * CC + lt0 + j;
            float ph = base_phases[l * 256 + d];
            float sp, cp; __sincosf(ph, &sp, &cp);
            float vp = g_vp[r * 256 + d];
            par += vp * cp; pai += vp * sp;
        }
    }
    int base = bc * 64 * 256;
    #pragma unroll
    for (int f = 0; f < 64; f++) g_S[base + f * 256 + d] = acc[f];
    g_psum[bc * 512 + d] = par;
    g_psum[bc * 512 + 256 + d] = pai;
}

// ================= Kernel 4: exclusive prefix over chunks =================
__global__ __launch_bounds__(256) void k4_prefix()
{
    int tid = threadIdx.x;
    if (blockIdx.x < 128) {
        int idx = blockIdx.x * 256 + tid;       // (b, f*256+d)
        int b = idx >> 14, rd = idx & 16383;
        float run = 0.f;
        #pragma unroll
        for (int c = 0; c < 16; c++) {
            int off = (b * 16 + c) * 16384 + rd;
            g_P[off] = run;
            run += g_S[off];
        }
    } else {
        int e = (blockIdx.x - 128) * 256 + tid;
        if (e < 1024) {
            int b = e >> 9, rd = e & 511;
            float run = 0.f;
            #pragma unroll
            for (int c = 0; c < 16; c++) {
                int off = (b * 16 + c) * 512 + rd;
                g_pprefix[off] = run;
                run += g_psum[off];
            }
        }
    }
}

// ================= Kernel 5: intra-chunk masked scores =================
__global__ __launch_bounds__(256) void k5_scores()
{
    __shared__ float qs[16][128];
    __shared__ float ks[16][128];
    int bc = blockIdx.x; int b = bc >> 4, c = bc & 15;
    int row0 = b * LL + c * CC;
    int tid = threadIdx.x;
    int ty = tid >> 4, tx = tid & 15;
    float acc[8][8] = {};
    for (int f0 = 0; f0 < 64; f0 += 16) {
        __syncthreads();
        #pragma unroll
        for (int it = 0; it < 2; it++) {
            int idx = tid + it * 256;
            int l = idx >> 2, kq = (idx & 3) * 4;
            float4 v = *(const float4*)&g_qf[(row0 + l) * 64 + f0 + kq];
            qs[kq+0][l] = v.x; qs[kq+1][l] = v.y; qs[kq+2][l] = v.z; qs[kq+3][l] = v.w;
            float4 u = *(const float4*)&g_kf[(row0 + l) * 64 + f0 + kq];
            ks[kq+0][l] = u.x; ks[kq+1][l] = u.y; ks[kq+2][l] = u.z; ks[kq+3][l] = u.w;
        }
        __syncthreads();
        #pragma unroll
        for (int kk = 0; kk < 16; kk++) {
            float4 a0 = *(const float4*)&qs[kk][ty*8];
            float4 a1 = *(const float4*)&qs[kk][ty*8+4];
            float4 b0 = *(const float4*)&ks[kk][tx*8];
            float4 b1 = *(const float4*)&ks[kk][tx*8+4];
            float aa[8] = {a0.x,a0.y,a0.z,a0.w,a1.x,a1.y,a1.z,a1.w};
            float bb[8] = {b0.x,b0.y,b0.z,b0.w,b1.x,b1.y,b1.z,b1.w};
            #pragma unroll
            for (int i = 0; i < 8; i++)
                #pragma unroll
                for (int j = 0; j < 8; j++)
                    acc[i][j] += aa[i] * bb[j];
        }
    }
    int sb = bc * CC * CC;
    #pragma unroll
    for (int i = 0; i < 8; i++) {
        int l = ty*8 + i;
        #pragma unroll
        for (int j = 0; j < 8; j++) {
            int jj = tx*8 + j;
            g_scores[sb + l*128 + jj] = (jj <= l) ? acc[i][j] : 0.f;
        }
    }
}

// ================= Kernel 6: content output: [qf | scores] @ [P ; vc] =================
__global__ __launch_bounds__(256) void k6_content()
{
    __shared__ float As[16][128];
    __shared__ float Bs[16][64];
    int bc = blockIdx.x; int b = bc >> 4, c = bc & 15;
    int dt = blockIdx.y; int d0 = dt * 64;
    int row0 = b * LL + c * CC;
    int tid = threadIdx.x;
    int ty = tid >> 4, tx = tid & 15;  // rows ty*8.., cols tx*4..
    float acc[8][4] = {};
    int Pbase = bc * 64 * 256;
    int sbase = bc * CC * CC;
    for (int k0 = 0; k0 < 192; k0 += 16) {
        __syncthreads();
        #pragma unroll
        for (int it = 0; it < 2; it++) {
            int idx = tid + it * 256;
            int l = idx >> 2, kq = (idx & 3) * 4;
            int kg = k0 + kq;
            float4 v;
            if (kg < 64) v = *(const float4*)&g_qf[(row0 + l) * 64 + kg];
            else         v = *(const float4*)&g_scores[sbase + l * 128 + (kg - 64)];
            As[kq+0][l] = v.x; As[kq+1][l] = v.y; As[kq+2][l] = v.z; As[kq+3][l] = v.w;
        }
        {
            int kr = tid >> 4, c4 = (tid & 15) * 4;
            int kg = k0 + kr;
            float4 v;
            if (kg < 64) v = *(const float4*)&g_P[Pbase + kg * 256 + d0 + c4];
            else         v = *(const float4*)&g_vc[(row0 + kg - 64) * 256 + d0 + c4];
            *(float4*)&Bs[kr][c4] = v;
        }
        __syncthreads();
        #pragma unroll
        for (int kk = 0; kk < 16; kk++) {
            float4 a0 = *(const float4*)&As[kk][ty*8];
            float4 a1 = *(const float4*)&As[kk][ty*8+4];
            float4 b0 = *(const float4*)&Bs[kk][tx*4];
            float aa[8] = {a0.x,a0.y,a0.z,a0.w,a1.x,a1.y,a1.z,a1.w};
            float bb[4] = {b0.x,b0.y,b0.z,b0.w};
            #pragma unroll
            for (int i = 0; i < 8; i++)
                #pragma unroll
                for (int j = 0; j < 4; j++)
                    acc[i][j] += aa[i] * bb[j];
        }
    }
    #pragma unroll
    for (int i = 0; i < 8; i++) {
        int l = ty*8 + i;
        float scale = rsqrtf((float)((c*CC + l + 1) * KK));
        #pragma unroll
        for (int j = 0; j < 4; j++) {
            g_cont[(row0 + l) * 256 + d0 + tx*4 + j] = acc[i][j] * scale;
        }
    }
}

// ================= Kernel 7: pos scan + gate combine + LayerNorm =================
__global__ __launch_bounds__(256) void k7_poscomb(
    const float* __restrict__ base_phases,
    const float* __restrict__ ln_g, const float* __restrict__ ln_b)
{
    __shared__ float comb[32][257];
    int bc = blockIdx.x; int b = bc >> 4, c = bc & 15;
    int row0 = b * LL + c * CC;
    int d = threadIdx.x;
    float ar = g_pprefix[bc * 512 + d];
    float ai = g_pprefix[bc * 512 + 256 + d];
    int w = d >> 5, lane = d & 31;
    for (int t = 0; t < 4; t++) {
        for (int lt = 0; lt < 32; lt++) {
            int l = c*CC + t*32 + lt;
            int r = row0 + t*32 + lt;
            float ph = base_phases[l*256 + d];
            float sp, cp; __sincosf(ph, &sp, &cp);
            float v = g_vp[r*256 + d];
            ar += v * cp; ai += v * sp;
            float pret = (ar*cp + ai*sp) * rsqrtf((float)(l + 1));
            float g0 = g_gates[r*2], g1v = g_gates[r*2+1];
            float cv = g_cont[r*256 + d];
            comb[lt][d] = g0 * pret + g1v * cv;
        }
        __syncthreads();
        #pragma unroll
        for (int q = 0; q < 4; q++) {
            int lt = w*4 + q;
            int r = row0 + t*32 + lt;
            float vals[8]; float s1 = 0.f, s2 = 0.f;
            #pragma unroll
            for (int k = 0; k < 8; k++) {
                float v = comb[lt][lane + 32*k];
                vals[k] = v; s1 += v; s2 += v*v;
            }
            #pragma unroll
            for (int off = 16; off; off >>= 1) {
                s1 += __shfl_xor_sync(~0u, s1, off);
                s2 += __shfl_xor_sync(~0u, s2, off);
            }
            float mu = s1 * (1.f/256.f);
            float var = s2 * (1.f/256.f) - mu*mu;
            float rstd = rsqrtf(var + 1e-5f);
            #pragma unroll
            for (int k = 0; k < 8; k++) {
                int dd = lane + 32*k;
                g_norm[r*256 + dd] = (vals[k] - mu) * rstd * ln_g[dd] + ln_b[dd];
            }
        }
        __syncthreads();
    }
}

// ================= Kernel 8: out = x + normed @ Wo + bo =================
__global__ __launch_bounds__(256) void k8_outgemm(
    const float* __restrict__ x, const float* __restrict__ Wo,
    const float* __restrict__ bo, float* __restrict__ out)
{
    __shared__ float As[16][64];
    __shared__ float Bs[16][64];
    int row0 = blockIdx.x * 64;
    int colbase = blockIdx.y * 64;
    int tid = threadIdx.x;
    int ty = tid >> 4, tx = tid & 15;
    int arow = tid >> 2, ak = (tid & 3) * 4;
    int bk = tid >> 4, bcid = (tid & 15) * 4;
    float acc[4][4] = {};
    for (int k0 = 0; k0 < 256; k0 += 16) {
        __syncthreads();
        float4 av = *(const float4*)&g_norm[(row0 + arow) * 256 + k0 + ak];
        As[ak+0][arow] = av.x; As[ak+1][arow] = av.y;
        As[ak+2][arow] = av.z; As[ak+3][arow] = av.w;
        float4 bv = *(const float4*)&Wo[(k0 + bk) * 256 + colbase + bcid];
        *(float4*)&Bs[bk][bcid] = bv;
        __syncthreads();
        #pragma unroll
        for (int kk = 0; kk < 16; kk++) {
            float4 a = *(const float4*)&As[kk][ty*4];
            float4 b = *(const float4*)&Bs[kk][tx*4];
            float aa[4] = {a.x, a.y, a.z, a.w};
            float bb[4] = {b.x, b.y, b.z, b.w};
            #pragma unroll
            for (int i = 0; i < 4; i++)
                #pragma unroll
                for (int j = 0; j < 4; j++)
                    acc[i][j] += aa[i] * bb[j];
        }
    }
    #pragma unroll
    for (int i = 0; i < 4; i++) {
        int r = row0 + ty*4 + i;
        #pragma unroll
        for (int j = 0; j < 4; j++) {
            int cc2 = colbase + tx*4 + j;
            out[r * 256 + cc2] = x[r * 256 + cc2] + acc[i][j] + bo[cc2];
        }
    }
}

// ================= launcher =================
extern "C" void kernel_launch(void* const* d_in, const int* in_sizes, int n_in,
                              void* d_out, int out_size)
{
    const float* x   = (const float*)d_in[0];
    const float* bp  = (const float*)d_in[1];
    const float* Wk1 = (const float*)d_in[2];
    const float* bk1 = (const float*)d_in[3];
    const float* Wk2 = (const float*)d_in[4];
    const float* bk2 = (const float*)d_in[5];
    const float* Wq1 = (const float*)d_in[6];
    const float* bq1 = (const float*)d_in[7];
    const float* Wq2 = (const float*)d_in[8];
    const float* bq2 = (const float*)d_in[9];
    const float* Wvc = (const float*)d_in[10];
    const float* bvc = (const float*)d_in[11];
    const float* Wvp = (const float*)d_in[12];
    const float* bvp = (const float*)d_in[13];
    const float* Wg1 = (const float*)d_in[14];
    const float* bg1 = (const float*)d_in[15];
    const float* Wg2 = (const float*)d_in[16];
    const float* bg2 = (const float*)d_in[17];
    const float* lng = (const float*)d_in[18];
    const float* lnb = (const float*)d_in[19];
    const float* Wo  = (const float*)d_in[20];
    const float* bo  = (const float*)d_in[21];
    float* out = (float*)d_out;

    k1_gemm<<<dim3(64, 17), 256>>>(x, Wk1, bk1, Wq1, bq1, Wvc, bvc, Wvp, bvp, Wg1, bg1);
    k2_phase<<<128, 256>>>(Wk2, bk2, Wq2, bq2, Wg2, bg2);
    k3_chunksum<<<32, 256>>>(bp);
    k4_prefix<<<132, 256>>>();
    k5_scores<<<32, 256>>>();
    k6_content<<<dim3(32, 4), 256>>>();
    k7_poscomb<<<32, 256>>>(bp, lng, lnb);
    k8_outgemm<<<dim3(64, 4), 256>>>(x, Wo, bo, out);
}

// round 2
// speedup vs baseline: 1.8198x; 1.8198x over previous
#include <cuda_runtime.h>
#include <cuda_bf16.h>
#include <math.h>

// Problem constants
#define Bb 2
#define LL 2048
#define DD 256
#define KK 32
#define FF 64          // 2*K feature dim
#define MM (Bb*LL)     // 4096 rows
#define CC 128         // chunk size
#define NC (LL/CC)     // 16 chunks per batch
#define PI_F 3.14159265358979323846f

// ---------------- scratch (device globals; no allocation allowed) ----------------
__device__ float g_hk[MM*DD];
__device__ float g_hq[MM*DD];
__device__ float g_vc[MM*DD];
__device__ float g_vp[MM*DD];
__device__ float g_g1[MM*64];
__device__ float g_kf[MM*FF];
__device__ float g_qf[MM*FF];
__device__ float g_gates[MM*2];
__device__ float g_Spart[Bb*NC*4*FF*DD];   // per-32-row content state partials
__device__ float g_P[Bb*NC*FF*DD];         // chunk-level exclusive prefix of states
__device__ float g_psum[Bb*64*2*DD];       // per-32-row pos partial sums (real, imag)
__device__ float g_pprefix[Bb*64*2*DD];    // exclusive prefix at 32-row granularity
__device__ float g_scores[Bb*NC*CC*CC];    // intra-chunk masked scores
__device__ float g_cont[MM*DD];
__device__ float g_norm[MM*DD];

// ---------------- tf32 helpers ----------------
__device__ __forceinline__ float f2tf32f(float f) {
    unsigned u;
    asm("cvt.rna.tf32.f32 %0, %1;" : "=r"(u) : "f"(f));
    return __uint_as_float(u);
}

__device__ __forceinline__ void mma_tf32(float c[4],
    unsigned a0, unsigned a1, unsigned a2, unsigned a3,
    unsigned b0, unsigned b1)
{
    asm volatile(
        "mma.sync.aligned.m16n8k8.row.col.f32.tf32.tf32.f32 "
        "{%0,%1,%2,%3}, {%4,%5,%6,%7}, {%8,%9}, {%0,%1,%2,%3};"
        : "+f"(c[0]), "+f"(c[1]), "+f"(c[2]), "+f"(c[3])
        : "r"(a0), "r"(a1), "r"(a2), "r"(a3), "r"(b0), "r"(b1));
}

// ================= Kernel 1: fused first-layer GEMMs (tf32 mma) =================
// segments: [hk(256,tanh)|hq(256,tanh)|vc(256)|vp(256)|g1(64,relu)]
__global__ __launch_bounds__(256) void k1_mma(
    const float* __restrict__ x,
    const float* __restrict__ Wk1, const float* __restrict__ bk1,
    const float* __restrict__ Wq1, const float* __restrict__ bq1,
    const float* __restrict__ Wvc, const float* __restrict__ bvc,
    const float* __restrict__ Wvp, const float* __restrict__ bvp,
    const float* __restrict__ Wg1, const float* __restrict__ bg1)
{
    __shared__ float As[128][20];
    __shared__ float Bs[16][68];
    int ct = blockIdx.y;
    const float* W; const float* bias; float* outp; int Nseg; int act; int colbase;
    if (ct < 16) {
        int seg = ct >> 2;
        colbase = (ct & 3) * 64;
        Nseg = 256;
        if (seg == 0)      { W = Wk1; bias = bk1; outp = g_hk; act = 1; }
        else if (seg == 1) { W = Wq1; bias = bq1; outp = g_hq; act = 1; }
        else if (seg == 2) { W = Wvc; bias = bvc; outp = g_vc; act = 0; }
        else               { W = Wvp; bias = bvp; outp = g_vp; act = 0; }
    } else {
        W = Wg1; bias = bg1; outp = g_g1; Nseg = 64; act = 2; colbase = 0;
    }
    int row0 = blockIdx.x * 128;
    int tid = threadIdx.x;
    int w = tid >> 5, lane = tid & 31;
    int wm = (w & 3) * 32;
    int wn = (w >> 2) * 32;
    int lq = lane >> 2, lr = lane & 3;
    float c[2][4][4] = {};
    for (int k0 = 0; k0 < 256; k0 += 16) {
        __syncthreads();
        #pragma unroll
        for (int it = 0; it < 2; it++) {
            int idx = tid + it * 256;
            int r = idx >> 2, c4 = (idx & 3) * 4;
            float4 v = *(const float4*)&x[(row0 + r) * 256 + k0 + c4];
            As[r][c4+0] = f2tf32f(v.x); As[r][c4+1] = f2tf32f(v.y);
            As[r][c4+2] = f2tf32f(v.z); As[r][c4+3] = f2tf32f(v.w);
        }
        {
            int r = tid >> 4, c4 = (tid & 15) * 4;
            float4 v = *(const float4*)&W[(k0 + r) * Nseg + colbase + c4];
            Bs[r][c4+0] = f2tf32f(v.x); Bs[r][c4+1] = f2tf32f(v.y);
            Bs[r][c4+2] = f2tf32f(v.z); Bs[r][c4+3] = f2tf32f(v.w);
        }
        __syncthreads();
        #pragma unroll
        for (int ks = 0; ks < 2; ks++) {
            unsigned a[2][4];
            #pragma unroll
            for (int mt = 0; mt < 2; mt++) {
                int rr = wm + mt*16 + lq;
                int cc = ks*8 + lr;
                a[mt][0] = __float_as_uint(As[rr][cc]);
                a[mt][1] = __float_as_uint(As[rr+8][cc]);
                a[mt][2] = __float_as_uint(As[rr][cc+4]);
                a[mt][3] = __float_as_uint(As[rr+8][cc+4]);
            }
            #pragma unroll
            for (int nt = 0; nt < 4; nt++) {
                int bk = ks*8 + lr;
                int bn = wn + nt*8 + lq;
                unsigned b0 = __float_as_uint(Bs[bk][bn]);
                unsigned b1 = __float_as_uint(Bs[bk+4][bn]);
                #pragma unroll
                for (int mt = 0; mt < 2; mt++)
                    mma_tf32(c[mt][nt], a[mt][0], a[mt][1], a[mt][2], a[mt][3], b0, b1);
            }
        }
    }
    #pragma unroll
    for (int mt = 0; mt < 2; mt++) {
        #pragma unroll
        for (int nt = 0; nt < 4; nt++) {
            int r = row0 + wm + mt*16 + lq;
            int cc = colbase + wn + nt*8 + lr*2;
            float b0v = bias[cc], b1v = bias[cc+1];
            float v00 = c[mt][nt][0] + b0v, v01 = c[mt][nt][1] + b1v;
            float v10 = c[mt][nt][2] + b0v, v11 = c[mt][nt][3] + b1v;
            if (act == 1) { v00 = tanhf(v00); v01 = tanhf(v01); v10 = tanhf(v10); v11 = tanhf(v11); }
            else if (act == 2) { v00 = fmaxf(v00,0.f); v01 = fmaxf(v01,0.f); v10 = fmaxf(v10,0.f); v11 = fmaxf(v11,0.f); }
            *(float2*)&outp[r * Nseg + cc] = make_float2(v00, v01);
            *(float2*)&outp[(r+8) * Nseg + cc] = make_float2(v10, v11);
        }
    }
}

// ================= Kernel 2: phase features + gates =================
__global__ __launch_bounds__(256) void k2_phase(
    const float* __restrict__ Wk2, const float* __restrict__ bk2,
    const float* __restrict__ Wq2, const float* __restrict__ bq2,
    const float* __restrict__ Wg2, const float* __restrict__ bg2)
{
    __shared__ float Ws[256*32];
    __shared__ float rowbuf[8][256];
    __shared__ float Wg2s[128];
    int tid = threadIdx.x;
    int w = tid >> 5, lane = tid & 31;
    int rowbase = blockIdx.x * 32;
    if (tid < 128) Wg2s[tid] = Wg2[tid];

    for (int pass = 0; pass < 2; pass++) {
        const float* Wmat = pass ? Wq2 : Wk2;
        const float* bvec = pass ? bq2 : bk2;
        const float* hsrc = pass ? g_hq : g_hk;
        float* fdst = pass ? g_qf : g_kf;
        __syncthreads();
        for (int i = tid; i < 8192; i += 256) Ws[i] = Wmat[i];
        __syncthreads();
        for (int rr = 0; rr < 4; rr++) {
            int r = rowbase + w * 4 + rr;
            for (int i = lane; i < 256; i += 32) rowbuf[w][i] = hsrc[r*256 + i];
            __syncwarp();
            float s0 = 0.f, s1 = 0.f, s2 = 0.f, s3 = 0.f;
            #pragma unroll 4
            for (int i = 0; i < 256; i += 4) {
                s0 += rowbuf[w][i+0] * Ws[(i+0)*32 + lane];
                s1 += rowbuf[w][i+1] * Ws[(i+1)*32 + lane];
                s2 += rowbuf[w][i+2] * Ws[(i+2)*32 + lane];
                s3 += rowbuf[w][i+3] * Ws[(i+3)*32 + lane];
            }
            float s = bvec[lane] + ((s0 + s1) + (s2 + s3));
            float ph = tanhf(s) * PI_F;
            float sp, cp; __sincosf(ph, &sp, &cp);
            fdst[r*64 + lane] = cp;
            fdst[r*64 + 32 + lane] = sp;
            __syncwarp();
        }
    }
    // gates
    for (int rr = 0; rr < 4; rr++) {
        int r = rowbase + w*4 + rr;
        float p0 = 0.f, p1 = 0.f;
        for (int i = lane; i < 64; i += 32) {
            float gv = g_g1[r*64 + i];
            p0 += gv * Wg2s[i*2 + 0];
            p1 += gv * Wg2s[i*2 + 1];
        }
        #pragma unroll
        for (int off = 16; off; off >>= 1) {
            p0 += __shfl_xor_sync(~0u, p0, off);
            p1 += __shfl_xor_sync(~0u, p1, off);
        }
        if (lane == 0) {
            float l0 = p0 + bg2[0], l1 = p1 + bg2[1];
            float m = fmaxf(l0, l1);
            float e0 = __expf(l0 - m), e1 = __expf(l1 - m);
            float inv = 1.f / (e0 + e1);
            g_gates[r*2 + 0] = e0 * inv;
            g_gates[r*2 + 1] = e1 * inv;
        }
    }
}

// ================= Kernel 3: per-32-row partial sums (content state + pos) =================
__global__ __launch_bounds__(256) void k3_chunksum(const float* __restrict__ base_phases)
{
    __shared__ float kfs[8][64];
    int blk = blockIdx.x;            // (b*16+c)*4 + t
    int bc = blk >> 2, t = blk & 3;
    int b = bc >> 4, c = bc & 15;
    int d = threadIdx.x;
    int row0 = b * LL + c * CC + t * 32;
    int l0 = c * CC + t * 32;
    float acc[64];
    #pragma unroll
    for (int f = 0; f < 64; f++) acc[f] = 0.f;
    float par = 0.f, pai = 0.f;
    for (int lt0 = 0; lt0 < 32; lt0 += 8) {
        __syncthreads();
        for (int i = d; i < 512; i += 256)
            kfs[i >> 6][i & 63] = g_kf[(row0 + lt0 + (i >> 6)) * 64 + (i & 63)];
        __syncthreads();
        #pragma unroll
        for (int j = 0; j < 8; j++) {
            int r = row0 + lt0 + j;
            float v = g_vc[r * 256 + d];
            #pragma unroll
            for (int f4 = 0; f4 < 16; f4++) {
                float4 kv = *(const float4*)&kfs[j][f4 * 4];
                acc[f4*4+0] += kv.x * v;
                acc[f4*4+1] += kv.y * v;
                acc[f4*4+2] += kv.z * v;
                acc[f4*4+3] += kv.w * v;
            }
            int l = l0 + lt0 + j;
            float ph = base_phases[l * 256 + d];
            float sp, cp; __sincosf(ph, &sp, &cp);
            float vp = g_vp[r * 256 + d];
            par += vp * cp; pai += vp * sp;
        }
    }
    int base = blk * 64 * 256;
    #pragma unroll
    for (int f = 0; f < 64; f++) g_Spart[base + f * 256 + d] = acc[f];
    int s = c * 4 + t;
    g_psum[(b * 64 + s) * 512 + d] = par;
    g_psum[(b * 64 + s) * 512 + 256 + d] = pai;
}

// ================= Kernel 4: exclusive prefixes (front-batched loads) =================
__global__ __launch_bounds__(256) void k4_prefix()
{
    int tid = threadIdx.x;
    if (blockIdx.x < 128) {
        int idx = blockIdx.x * 256 + tid;       // (b, f*256+d) -> 32768 chains
        int b = idx >> 14, rd = idx & 16383;
        float v[64];
        #pragma unroll
        for (int c = 0; c < 16; c++)
            #pragma unroll
            for (int t = 0; t < 4; t++)
                v[c*4+t] = g_Spart[(((b * 16 + c) * 4) + t) * 16384 + rd];
        float run = 0.f;
        #pragma unroll
        for (int c = 0; c < 16; c++) {
            g_P[(b * 16 + c) * 16384 + rd] = run;
            run += (v[c*4] + v[c*4+1]) + (v[c*4+2] + v[c*4+3]);
        }
    } else {
        int e = (blockIdx.x - 128) * 256 + tid;
        if (e < 1024) {
            int b = e >> 9, rd = e & 511;
            float v[64];
            #pragma unroll
            for (int s = 0; s < 64; s++) v[s] = g_psum[(b * 64 + s) * 512 + rd];
            float run = 0.f;
            #pragma unroll
            for (int s = 0; s < 64; s++) {
                g_pprefix[(b * 64 + s) * 512 + rd] = run;
                run += v[s];
            }
        }
    }
}

// ================= Kernel 5: intra-chunk masked scores =================
__global__ __launch_bounds__(256) void k5_scores()
{
    __shared__ float qs[16][128];
    __shared__ float ks[16][128];
    int bc = blockIdx.x; int b = bc >> 4, c = bc & 15;
    int row0 = b * LL + c * CC;
    int tid = threadIdx.x;
    int ty = tid >> 4, tx = tid & 15;
    float acc[8][8] = {};
    for (int f0 = 0; f0 < 64; f0 += 16) {
        __syncthreads();
        #pragma unroll
        for (int it = 0; it < 2; it++) {
            int idx = tid + it * 256;
            int l = idx >> 2, kq = (idx & 3) * 4;
            float4 v = *(const float4*)&g_qf[(row0 + l) * 64 + f0 + kq];
            qs[kq+0][l] = v.x; qs[kq+1][l] = v.y; qs[kq+2][l] = v.z; qs[kq+3][l] = v.w;
            float4 u = *(const float4*)&g_kf[(row0 + l) * 64 + f0 + kq];
            ks[kq+0][l] = u.x; ks[kq+1][l] = u.y; ks[kq+2][l] = u.z; ks[kq+3][l] = u.w;
        }
        __syncthreads();
        #pragma unroll
        for (int kk = 0; kk < 16; kk++) {
            float4 a0 = *(const float4*)&qs[kk][ty*8];
            float4 a1 = *(const float4*)&qs[kk][ty*8+4];
            float4 b0 = *(const float4*)&ks[kk][tx*8];
            float4 b1 = *(const float4*)&ks[kk][tx*8+4];
            float aa[8] = {a0.x,a0.y,a0.z,a0.w,a1.x,a1.y,a1.z,a1.w};
            float bb[8] = {b0.x,b0.y,b0.z,b0.w,b1.x,b1.y,b1.z,b1.w};
            #pragma unroll
            for (int i = 0; i < 8; i++)
                #pragma unroll
                for (int j = 0; j < 8; j++)
                    acc[i][j] += aa[i] * bb[j];
        }
    }
    int sb = bc * CC * CC;
    #pragma unroll
    for (int i = 0; i < 8; i++) {
        int l = ty*8 + i;
        #pragma unroll
        for (int j = 0; j < 8; j++) {
            int jj = tx*8 + j;
            g_scores[sb + l*128 + jj] = (jj <= l) ? acc[i][j] : 0.f;
        }
    }
}

// ================= Kernel 6: content output: [qf | scores] @ [P ; vc] =================
__global__ __launch_bounds__(256) void k6_content()
{
    __shared__ float As[16][128];
    __shared__ float Bs[16][64];
    int bc = blockIdx.x; int b = bc >> 4, c = bc & 15;
    int dt = blockIdx.y; int d0 = dt * 64;
    int row0 = b * LL + c * CC;
    int tid = threadIdx.x;
    int ty = tid >> 4, tx = tid & 15;
    float acc[8][4] = {};
    int Pbase = bc * 64 * 256;
    int sbase = bc * CC * CC;
    for (int k0 = 0; k0 < 192; k0 += 16) {
        __syncthreads();
        #pragma unroll
        for (int it = 0; it < 2; it++) {
            int idx = tid + it * 256;
            int l = idx >> 2, kq = (idx & 3) * 4;
            int kg = k0 + kq;
            float4 v;
            if (kg < 64) v = *(const float4*)&g_qf[(row0 + l) * 64 + kg];
            else         v = *(const float4*)&g_scores[sbase + l * 128 + (kg - 64)];
            As[kq+0][l] = v.x; As[kq+1][l] = v.y; As[kq+2][l] = v.z; As[kq+3][l] = v.w;
        }
        {
            int kr = tid >> 4, c4 = (tid & 15) * 4;
            int kg = k0 + kr;
            float4 v;
            if (kg < 64) v = *(const float4*)&g_P[Pbase + kg * 256 + d0 + c4];
            else         v = *(const float4*)&g_vc[(row0 + kg - 64) * 256 + d0 + c4];
            *(float4*)&Bs[kr][c4] = v;
        }
        __syncthreads();
        #pragma unroll
        for (int kk = 0; kk < 16; kk++) {
            float4 a0 = *(const float4*)&As[kk][ty*8];
            float4 a1 = *(const float4*)&As[kk][ty*8+4];
            float4 b0 = *(const float4*)&Bs[kk][tx*4];
            float aa[8] = {a0.x,a0.y,a0.z,a0.w,a1.x,a1.y,a1.z,a1.w};
            float bb[4] = {b0.x,b0.y,b0.z,b0.w};
            #pragma unroll
            for (int i = 0; i < 8; i++)
                #pragma unroll
                for (int j = 0; j < 4; j++)
                    acc[i][j] += aa[i] * bb[j];
        }
    }
    #pragma unroll
    for (int i = 0; i < 8; i++) {
        int l = ty*8 + i;
        float scale = rsqrtf((float)((c*CC + l + 1) * KK));
        #pragma unroll
        for (int j = 0; j < 4; j++) {
            g_cont[(row0 + l) * 256 + d0 + tx*4 + j] = acc[i][j] * scale;
        }
    }
}

// ================= Kernel 7: pos scan (32 rows/block) + gate combine + LayerNorm =================
__global__ __launch_bounds__(256) void k7_poscomb(
    const float* __restrict__ base_phases,
    const float* __restrict__ ln_g, const float* __restrict__ ln_b)
{
    __shared__ float comb[32][257];
    int blk = blockIdx.x;           // (b*16+c)*4 + t
    int bc = blk >> 2, t = blk & 3;
    int b = bc >> 4, c = bc & 15;
    int row0 = b * LL + c * CC + t * 32;
    int l0 = c * CC + t * 32;
    int d = threadIdx.x;
    int s = c * 4 + t;
    float ar = g_pprefix[(b * 64 + s) * 512 + d];
    float ai = g_pprefix[(b * 64 + s) * 512 + 256 + d];
    int w = d >> 5, lane = d & 31;
    for (int lt = 0; lt < 32; lt++) {
        int l = l0 + lt;
        int r = row0 + lt;
        float ph = base_phases[l*256 + d];
        float sp, cp; __sincosf(ph, &sp, &cp);
        float v = g_vp[r*256 + d];
        ar += v * cp; ai += v * sp;
        float pret = (ar*cp + ai*sp) * rsqrtf((float)(l + 1));
        float g0 = g_gates[r*2], g1v = g_gates[r*2+1];
        float cv = g_cont[r*256 + d];
        comb[lt][d] = g0 * pret + g1v * cv;
    }
    __syncthreads();
    #pragma unroll
    for (int q = 0; q < 4; q++) {
        int lt = w*4 + q;
        int r = row0 + lt;
        float vals[8]; float s1 = 0.f, s2 = 0.f;
        #pragma unroll
        for (int k = 0; k < 8; k++) {
            float v = comb[lt][lane + 32*k];
            vals[k] = v; s1 += v; s2 += v*v;
        }
        #pragma unroll
        for (int off = 16; off; off >>= 1) {
            s1 += __shfl_xor_sync(~0u, s1, off);
            s2 += __shfl_xor_sync(~0u, s2, off);
        }
        float mu = s1 * (1.f/256.f);
        float var = s2 * (1.f/256.f) - mu*mu;
        float rstd = rsqrtf(var + 1e-5f);
        #pragma unroll
        for (int k = 0; k < 8; k++) {
            int dd = lane + 32*k;
            g_norm[r*256 + dd] = (vals[k] - mu) * rstd * ln_g[dd] + ln_b[dd];
        }
    }
}

// ================= Kernel 8: out = x + normed @ Wo + bo (tf32 mma) =================
__global__ __launch_bounds__(256) void k8_mma(
    const float* __restrict__ x, const float* __restrict__ Wo,
    const float* __restrict__ bo, float* __restrict__ out)
{
    __shared__ float As[128][20];
    __shared__ float Bs[16][68];
    int row0 = blockIdx.x * 128;
    int colbase = blockIdx.y * 64;
    int tid = threadIdx.x;
    int w = tid >> 5, lane = tid & 31;
    int wm = (w & 3) * 32;
    int wn = (w >> 2) * 32;
    int lq = lane >> 2, lr = lane & 3;
    float c[2][4][4] = {};
    for (int k0 = 0; k0 < 256; k0 += 16) {
        __syncthreads();
        #pragma unroll
        for (int it = 0; it < 2; it++) {
            int idx = tid + it * 256;
            int r = idx >> 2, c4 = (idx & 3) * 4;
            float4 v = *(const float4*)&g_norm[(row0 + r) * 256 + k0 + c4];
            As[r][c4+0] = f2tf32f(v.x); As[r][c4+1] = f2tf32f(v.y);
            As[r][c4+2] = f2tf32f(v.z); As[r][c4+3] = f2tf32f(v.w);
        }
        {
            int r = tid >> 4, c4 = (tid & 15) * 4;
            float4 v = *(const float4*)&Wo[(k0 + r) * 256 + colbase + c4];
            Bs[r][c4+0] = f2tf32f(v.x); Bs[r][c4+1] = f2tf32f(v.y);
            Bs[r][c4+2] = f2tf32f(v.z); Bs[r][c4+3] = f2tf32f(v.w);
        }
        __syncthreads();
        #pragma unroll
        for (int ks = 0; ks < 2; ks++) {
            unsigned a[2][4];
            #pragma unroll
            for (int mt = 0; mt < 2; mt++) {
                int rr = wm + mt*16 + lq;
                int cc = ks*8 + lr;
                a[mt][0] = __float_as_uint(As[rr][cc]);
                a[mt][1] = __float_as_uint(As[rr+8][cc]);
                a[mt][2] = __float_as_uint(As[rr][cc+4]);
                a[mt][3] = __float_as_uint(As[rr+8][cc+4]);
            }
            #pragma unroll
            for (int nt = 0; nt < 4; nt++) {
                int bk = ks*8 + lr;
                int bn = wn + nt*8 + lq;
                unsigned b0 = __float_as_uint(Bs[bk][bn]);
                unsigned b1 = __float_as_uint(Bs[bk+4][bn]);
                #pragma unroll
                for (int mt = 0; mt < 2; mt++)
                    mma_tf32(c[mt][nt], a[mt][0], a[mt][1], a[mt][2], a[mt][3], b0, b1);
            }
        }
    }
    #pragma unroll
    for (int mt = 0; mt < 2; mt++) {
        #pragma unroll
        for (int nt = 0; nt < 4; nt++) {
            int r = row0 + wm + mt*16 + lq;
            int cc = colbase + wn + nt*8 + lr*2;
            float b0v = bo[cc], b1v = bo[cc+1];
            float2 x0 = *(const float2*)&x[r * 256 + cc];
            float2 x1 = *(const float2*)&x[(r+8) * 256 + cc];
            *(float2*)&out[r * 256 + cc] =
                make_float2(c[mt][nt][0] + b0v + x0.x, c[mt][nt][1] + b1v + x0.y);
            *(float2*)&out[(r+8) * 256 + cc] =
                make_float2(c[mt][nt][2] + b0v + x1.x, c[mt][nt][3] + b1v + x1.y);
        }
    }
}

// ================= launcher =================
extern "C" void kernel_launch(void* const* d_in, const int* in_sizes, int n_in,
                              void* d_out, int out_size)
{
    const float* x   = (const float*)d_in[0];
    const float* bp  = (const float*)d_in[1];
    const float* Wk1 = (const float*)d_in[2];
    const float* bk1 = (const float*)d_in[3];
    const float* Wk2 = (const float*)d_in[4];
    const float* bk2 = (const float*)d_in[5];
    const float* Wq1 = (const float*)d_in[6];
    const float* bq1 = (const float*)d_in[7];
    const float* Wq2 = (const float*)d_in[8];
    const float* bq2 = (const float*)d_in[9];
    const float* Wvc = (const float*)d_in[10];
    const float* bvc = (const float*)d_in[11];
    const float* Wvp = (const float*)d_in[12];
    const float* bvp = (const float*)d_in[13];
    const float* Wg1 = (const float*)d_in[14];
    const float* bg1 = (const float*)d_in[15];
    const float* Wg2 = (const float*)d_in[16];
    const float* bg2 = (const float*)d_in[17];
    const float* lng = (const float*)d_in[18];
    const float* lnb = (const float*)d_in[19];
    const float* Wo  = (const float*)d_in[20];
    const float* bo  = (const float*)d_in[21];
    float* out = (float*)d_out;

    k1_mma<<<dim3(32, 17), 256>>>(x, Wk1, bk1, Wq1, bq1, Wvc, bvc, Wvp, bvp, Wg1, bg1);
    k2_phase<<<128, 256>>>(Wk2, bk2, Wq2, bq2, Wg2, bg2);
    k3_chunksum<<<128, 256>>>(bp);
    k4_prefix<<<132, 256>>>();
    k5_scores<<<32, 256>>>();
    k6_content<<<dim3(32, 4), 256>>>();
    k7_poscomb<<<128, 256>>>(bp, lng, lnb);
    k8_mma<<<dim3(32, 4), 256>>>(x, Wo, bo, out);
}

// round 3
// speedup vs baseline: 2.1711x; 1.1930x over previous
#include <cuda_runtime.h>
#include <cuda_bf16.h>
#include <math.h>

// Problem constants
#define Bb 2
#define LL 2048
#define DD 256
#define KK 32
#define FF 64          // 2*K feature dim
#define MM (Bb*LL)     // 4096 rows
#define CC 128         // chunk size
#define NC (LL/CC)     // 16 chunks per batch
#define PI_F 3.14159265358979323846f

// ---------------- scratch (device globals; no allocation allowed) ----------------
__device__ float g_hk[MM*DD];
__device__ float g_hq[MM*DD];
__device__ float g_vc[MM*DD];
__device__ float g_vp[MM*DD];
__device__ float g_g1[MM*64];
__device__ float g_kf[MM*FF];
__device__ float g_qf[MM*FF];
__device__ float g_gates[MM*2];
__device__ float g_Spart[Bb*NC*4*FF*DD];   // per-32-row content state partials
__device__ float g_P[Bb*NC*FF*DD];         // chunk-level exclusive prefix of states
__device__ float g_psum[Bb*64*2*DD];       // per-32-row pos partial sums (real, imag)
__device__ float g_pprefix[Bb*64*2*DD];    // exclusive prefix at 32-row granularity
__device__ float g_scores[Bb*NC*CC*CC];    // intra-chunk masked scores
__device__ float g_cont[MM*DD];
__device__ float g_norm[MM*DD];

// ---------------- tf32 helpers ----------------
__device__ __forceinline__ float f2tf32f(float f) {
    unsigned u;
    asm("cvt.rna.tf32.f32 %0, %1;" : "=r"(u) : "f"(f));
    return __uint_as_float(u);
}

__device__ __forceinline__ void mma_tf32(float c[4],
    unsigned a0, unsigned a1, unsigned a2, unsigned a3,
    unsigned b0, unsigned b1)
{
    asm volatile(
        "mma.sync.aligned.m16n8k8.row.col.f32.tf32.tf32.f32 "
        "{%0,%1,%2,%3}, {%4,%5,%6,%7}, {%8,%9}, {%0,%1,%2,%3};"
        : "+f"(c[0]), "+f"(c[1]), "+f"(c[2]), "+f"(c[3])
        : "r"(a0), "r"(a1), "r"(a2), "r"(a3), "r"(b0), "r"(b1));
}

// ================= Kernel 1: fused first-layer GEMMs (tf32 mma, double-buffered) ===
// segments: [hk(256,tanh)|hq(256,tanh)|vc(256)|vp(256)|g1(64,relu)]
__global__ __launch_bounds__(256) void k1_mma(
    const float* __restrict__ x,
    const float* __restrict__ Wk1, const float* __restrict__ bk1,
    const float* __restrict__ Wq1, const float* __restrict__ bq1,
    const float* __restrict__ Wvc, const float* __restrict__ bvc,
    const float* __restrict__ Wvp, const float* __restrict__ bvp,
    const float* __restrict__ Wg1, const float* __restrict__ bg1)
{
    __shared__ float As[2][128][20];
    __shared__ float Bs[2][16][68];
    int ct = blockIdx.y;
    const float* W; const float* bias; float* outp; int Nseg; int act; int colbase;
    if (ct < 16) {
        int seg = ct >> 2;
        colbase = (ct & 3) * 64;
        Nseg = 256;
        if (seg == 0)      { W = Wk1; bias = bk1; outp = g_hk; act = 1; }
        else if (seg == 1) { W = Wq1; bias = bq1; outp = g_hq; act = 1; }
        else if (seg == 2) { W = Wvc; bias = bvc; outp = g_vc; act = 0; }
        else               { W = Wvp; bias = bvp; outp = g_vp; act = 0; }
    } else {
        W = Wg1; bias = bg1; outp = g_g1; Nseg = 64; act = 2; colbase = 0;
    }
    int row0 = blockIdx.x * 128;
    int tid = threadIdx.x;
    int w = tid >> 5, lane = tid & 31;
    int wm = (w & 3) * 32;
    int wn = (w >> 2) * 32;
    int lq = lane >> 2, lr = lane & 3;
    int r0 = tid >> 2, c4 = (tid & 3) * 4;
    int br = tid >> 4, bc4 = (tid & 15) * 4;
    float c[2][4][4] = {};
    float4 av0, av1, bv;

    av0 = *(const float4*)&x[(row0 + r0) * 256 + c4];
    av1 = *(const float4*)&x[(row0 + r0 + 64) * 256 + c4];
    bv  = *(const float4*)&W[br * Nseg + colbase + bc4];
    As[0][r0][c4+0]=f2tf32f(av0.x); As[0][r0][c4+1]=f2tf32f(av0.y);
    As[0][r0][c4+2]=f2tf32f(av0.z); As[0][r0][c4+3]=f2tf32f(av0.w);
    As[0][r0+64][c4+0]=f2tf32f(av1.x); As[0][r0+64][c4+1]=f2tf32f(av1.y);
    As[0][r0+64][c4+2]=f2tf32f(av1.z); As[0][r0+64][c4+3]=f2tf32f(av1.w);
    Bs[0][br][bc4+0]=f2tf32f(bv.x); Bs[0][br][bc4+1]=f2tf32f(bv.y);
    Bs[0][br][bc4+2]=f2tf32f(bv.z); Bs[0][br][bc4+3]=f2tf32f(bv.w);
    __syncthreads();

    for (int s = 0; s < 16; s++) {
        int cur = s & 1;
        if (s < 15) {
            int kn = (s + 1) * 16;
            av0 = *(const float4*)&x[(row0 + r0) * 256 + kn + c4];
            av1 = *(const float4*)&x[(row0 + r0 + 64) * 256 + kn + c4];
            bv  = *(const float4*)&W[(kn + br) * Nseg + colbase + bc4];
        }
        #pragma unroll
        for (int ks = 0; ks < 2; ks++) {
            unsigned a[2][4];
            #pragma unroll
            for (int mt = 0; mt < 2; mt++) {
                int rr = wm + mt*16 + lq;
                int cc = ks*8 + lr;
                a[mt][0] = __float_as_uint(As[cur][rr][cc]);
                a[mt][1] = __float_as_uint(As[cur][rr+8][cc]);
                a[mt][2] = __float_as_uint(As[cur][rr][cc+4]);
                a[mt][3] = __float_as_uint(As[cur][rr+8][cc+4]);
            }
            #pragma unroll
            for (int nt = 0; nt < 4; nt++) {
                int bn = wn + nt*8 + lq;
                unsigned b0 = __float_as_uint(Bs[cur][ks*8+lr][bn]);
                unsigned b1 = __float_as_uint(Bs[cur][ks*8+lr+4][bn]);
                #pragma unroll
                for (int mt = 0; mt < 2; mt++)
                    mma_tf32(c[mt][nt], a[mt][0], a[mt][1], a[mt][2], a[mt][3], b0, b1);
            }
        }
        if (s < 15) {
            int nb = cur ^ 1;
            As[nb][r0][c4+0]=f2tf32f(av0.x); As[nb][r0][c4+1]=f2tf32f(av0.y);
            As[nb][r0][c4+2]=f2tf32f(av0.z); As[nb][r0][c4+3]=f2tf32f(av0.w);
            As[nb][r0+64][c4+0]=f2tf32f(av1.x); As[nb][r0+64][c4+1]=f2tf32f(av1.y);
            As[nb][r0+64][c4+2]=f2tf32f(av1.z); As[nb][r0+64][c4+3]=f2tf32f(av1.w);
            Bs[nb][br][bc4+0]=f2tf32f(bv.x); Bs[nb][br][bc4+1]=f2tf32f(bv.y);
            Bs[nb][br][bc4+2]=f2tf32f(bv.z); Bs[nb][br][bc4+3]=f2tf32f(bv.w);
        }
        __syncthreads();
    }
    #pragma unroll
    for (int mt = 0; mt < 2; mt++) {
        #pragma unroll
        for (int nt = 0; nt < 4; nt++) {
            int r = row0 + wm + mt*16 + lq;
            int cc = colbase + wn + nt*8 + lr*2;
            float b0v = bias[cc], b1v = bias[cc+1];
            float v00 = c[mt][nt][0] + b0v, v01 = c[mt][nt][1] + b1v;
            float v10 = c[mt][nt][2] + b0v, v11 = c[mt][nt][3] + b1v;
            if (act == 1) { v00 = tanhf(v00); v01 = tanhf(v01); v10 = tanhf(v10); v11 = tanhf(v11); }
            else if (act == 2) { v00 = fmaxf(v00,0.f); v01 = fmaxf(v01,0.f); v10 = fmaxf(v10,0.f); v11 = fmaxf(v11,0.f); }
            *(float2*)&outp[r * Nseg + cc] = make_float2(v00, v01);
            *(float2*)&outp[(r+8) * Nseg + cc] = make_float2(v10, v11);
        }
    }
}

// ================= Kernel 2: phase features (tf32 mma) + gates =================
// warps 0-3: hk@Wk2 -> kf ; warps 4-7: hq@Wq2 -> qf
__global__ __launch_bounds__(256) void k2_mma(
    const float* __restrict__ Wk2, const float* __restrict__ bk2,
    const float* __restrict__ Wq2, const float* __restrict__ bq2,
    const float* __restrict__ Wg2, const float* __restrict__ bg2)
{
    __shared__ float Ak[2][128][17];
    __shared__ float Aq[2][128][17];
    __shared__ float Bs[2][16][68];
    int tid = threadIdx.x;
    int w = tid >> 5, lane = tid & 31;
    int row0 = blockIdx.x * 128;
    int wm = (w & 3) * 32;
    bool isq = (w >= 4);
    int lq = lane >> 2, lr = lane & 3;
    int r0 = tid >> 2, c4 = (tid & 3) * 4;
    int br = tid >> 4, bc4 = (tid & 15) * 4;
    float c[2][4][4] = {};
    float4 ak0, ak1, aq0, aq1, bv;

    ak0 = *(const float4*)&g_hk[(row0 + r0) * 256 + c4];
    ak1 = *(const float4*)&g_hk[(row0 + r0 + 64) * 256 + c4];
    aq0 = *(const float4*)&g_hq[(row0 + r0) * 256 + c4];
    aq1 = *(const float4*)&g_hq[(row0 + r0 + 64) * 256 + c4];
    bv  = (bc4 < 32) ? *(const float4*)&Wk2[br * 32 + bc4]
                     : *(const float4*)&Wq2[br * 32 + bc4 - 32];
    {
        Ak[0][r0][c4+0]=f2tf32f(ak0.x); Ak[0][r0][c4+1]=f2tf32f(ak0.y);
        Ak[0][r0][c4+2]=f2tf32f(ak0.z); Ak[0][r0][c4+3]=f2tf32f(ak0.w);
        Ak[0][r0+64][c4+0]=f2tf32f(ak1.x); Ak[0][r0+64][c4+1]=f2tf32f(ak1.y);
        Ak[0][r0+64][c4+2]=f2tf32f(ak1.z); Ak[0][r0+64][c4+3]=f2tf32f(ak1.w);
        Aq[0][r0][c4+0]=f2tf32f(aq0.x); Aq[0][r0][c4+1]=f2tf32f(aq0.y);
        Aq[0][r0][c4+2]=f2tf32f(aq0.z); Aq[0][r0][c4+3]=f2tf32f(aq0.w);
        Aq[0][r0+64][c4+0]=f2tf32f(aq1.x); Aq[0][r0+64][c4+1]=f2tf32f(aq1.y);
        Aq[0][r0+64][c4+2]=f2tf32f(aq1.z); Aq[0][r0+64][c4+3]=f2tf32f(aq1.w);
        Bs[0][br][bc4+0]=f2tf32f(bv.x); Bs[0][br][bc4+1]=f2tf32f(bv.y);
        Bs[0][br][bc4+2]=f2tf32f(bv.z); Bs[0][br][bc4+3]=f2tf32f(bv.w);
    }
    __syncthreads();

    for (int s = 0; s < 16; s++) {
        int cur = s & 1;
        if (s < 15) {
            int kn = (s + 1) * 16;
            ak0 = *(const float4*)&g_hk[(row0 + r0) * 256 + kn + c4];
            ak1 = *(const float4*)&g_hk[(row0 + r0 + 64) * 256 + kn + c4];
            aq0 = *(const float4*)&g_hq[(row0 + r0) * 256 + kn + c4];
            aq1 = *(const float4*)&g_hq[(row0 + r0 + 64) * 256 + kn + c4];
            bv  = (bc4 < 32) ? *(const float4*)&Wk2[(kn + br) * 32 + bc4]
                             : *(const float4*)&Wq2[(kn + br) * 32 + bc4 - 32];
        }
        const float (*A)[17] = isq ? Aq[cur] : Ak[cur];
        #pragma unroll
        for (int ks = 0; ks < 2; ks++) {
            unsigned a[2][4];
            #pragma unroll
            for (int mt = 0; mt < 2; mt++) {
                int rr = wm + mt*16 + lq;
                int cc = ks*8 + lr;
                a[mt][0] = __float_as_uint(A[rr][cc]);
                a[mt][1] = __float_as_uint(A[rr+8][cc]);
                a[mt][2] = __float_as_uint(A[rr][cc+4]);
                a[mt][3] = __float_as_uint(A[rr+8][cc+4]);
            }
            #pragma unroll
            for (int nt = 0; nt < 4; nt++) {
                int bn = (isq ? 32 : 0) + nt*8 + lq;
                unsigned b0 = __float_as_uint(Bs[cur][ks*8+lr][bn]);
                unsigned b1 = __float_as_uint(Bs[cur][ks*8+lr+4][bn]);
                #pragma unroll
                for (int mt = 0; mt < 2; mt++)
                    mma_tf32(c[mt][nt], a[mt][0], a[mt][1], a[mt][2], a[mt][3], b0, b1);
            }
        }
        if (s < 15) {
            int nb = cur ^ 1;
            Ak[nb][r0][c4+0]=f2tf32f(ak0.x); Ak[nb][r0][c4+1]=f2tf32f(ak0.y);
            Ak[nb][r0][c4+2]=f2tf32f(ak0.z); Ak[nb][r0][c4+3]=f2tf32f(ak0.w);
            Ak[nb][r0+64][c4+0]=f2tf32f(ak1.x); Ak[nb][r0+64][c4+1]=f2tf32f(ak1.y);
            Ak[nb][r0+64][c4+2]=f2tf32f(ak1.z); Ak[nb][r0+64][c4+3]=f2tf32f(ak1.w);
            Aq[nb][r0][c4+0]=f2tf32f(aq0.x); Aq[nb][r0][c4+1]=f2tf32f(aq0.y);
            Aq[nb][r0][c4+2]=f2tf32f(aq0.z); Aq[nb][r0][c4+3]=f2tf32f(aq0.w);
            Aq[nb][r0+64][c4+0]=f2tf32f(aq1.x); Aq[nb][r0+64][c4+1]=f2tf32f(aq1.y);
            Aq[nb][r0+64][c4+2]=f2tf32f(aq1.z); Aq[nb][r0+64][c4+3]=f2tf32f(aq1.w);
            Bs[nb][br][bc4+0]=f2tf32f(bv.x); Bs[nb][br][bc4+1]=f2tf32f(bv.y);
            Bs[nb][br][bc4+2]=f2tf32f(bv.z); Bs[nb][br][bc4+3]=f2tf32f(bv.w);
        }
        __syncthreads();
    }

    const float* bvec = isq ? bq2 : bk2;
    float* fdst = isq ? g_qf : g_kf;
    #pragma unroll
    for (int mt = 0; mt < 2; mt++) {
        #pragma unroll
        for (int nt = 0; nt < 4; nt++) {
            int r = row0 + wm + mt*16 + lq;
            int cn = nt*8 + lr*2;
            float b0v = bvec[cn], b1v = bvec[cn+1];
            float ph;
            float sp, cp;
            ph = tanhf(c[mt][nt][0] + b0v) * PI_F; __sincosf(ph, &sp, &cp);
            fdst[r*64 + cn] = cp; fdst[r*64 + 32 + cn] = sp;
            ph = tanhf(c[mt][nt][1] + b1v) * PI_F; __sincosf(ph, &sp, &cp);
            fdst[r*64 + cn+1] = cp; fdst[r*64 + 32 + cn+1] = sp;
            ph = tanhf(c[mt][nt][2] + b0v) * PI_F; __sincosf(ph, &sp, &cp);
            fdst[(r+8)*64 + cn] = cp; fdst[(r+8)*64 + 32 + cn] = sp;
            ph = tanhf(c[mt][nt][3] + b1v) * PI_F; __sincosf(ph, &sp, &cp);
            fdst[(r+8)*64 + cn+1] = cp; fdst[(r+8)*64 + 32 + cn+1] = sp;
        }
    }
    // gates: each warp handles 16 rows
    for (int rr = 0; rr < 16; rr++) {
        int r = row0 + w*16 + rr;
        float p0 = 0.f, p1 = 0.f;
        #pragma unroll
        for (int i = lane; i < 64; i += 32) {
            float gv = g_g1[r*64 + i];
            p0 += gv * Wg2[i*2 + 0];
            p1 += gv * Wg2[i*2 + 1];
        }
        #pragma unroll
        for (int off = 16; off; off >>= 1) {
            p0 += __shfl_xor_sync(~0u, p0, off);
            p1 += __shfl_xor_sync(~0u, p1, off);
        }
        if (lane == 0) {
            float l0 = p0 + bg2[0], l1 = p1 + bg2[1];
            float m = fmaxf(l0, l1);
            float e0 = __expf(l0 - m), e1 = __expf(l1 - m);
            float inv = 1.f / (e0 + e1);
            g_gates[r*2 + 0] = e0 * inv;
            g_gates[r*2 + 1] = e1 * inv;
        }
    }
}

// ================= Kernel 3: per-32-row partial sums (content state + pos) =================
__global__ __launch_bounds__(256) void k3_chunksum(const float* __restrict__ base_phases)
{
    __shared__ float kfs[8][64];
    int blk = blockIdx.x;            // (b*16+c)*4 + t
    int bc = blk >> 2, t = blk & 3;
    int b = bc >> 4, c = bc & 15;
    int d = threadIdx.x;
    int row0 = b * LL + c * CC + t * 32;
    int l0 = c * CC + t * 32;
    float acc[64];
    #pragma unroll
    for (int f = 0; f < 64; f++) acc[f] = 0.f;
    float par = 0.f, pai = 0.f;
    for (int lt0 = 0; lt0 < 32; lt0 += 8) {
        __syncthreads();
        for (int i = d; i < 512; i += 256)
            kfs[i >> 6][i & 63] = g_kf[(row0 + lt0 + (i >> 6)) * 64 + (i & 63)];
        __syncthreads();
        #pragma unroll
        for (int j = 0; j < 8; j++) {
            int r = row0 + lt0 + j;
            float v = g_vc[r * 256 + d];
            #pragma unroll
            for (int f4 = 0; f4 < 16; f4++) {
                float4 kv = *(const float4*)&kfs[j][f4 * 4];
                acc[f4*4+0] += kv.x * v;
                acc[f4*4+1] += kv.y * v;
                acc[f4*4+2] += kv.z * v;
                acc[f4*4+3] += kv.w * v;
            }
            int l = l0 + lt0 + j;
            float ph = base_phases[l * 256 + d];
            float sp, cp; __sincosf(ph, &sp, &cp);
            float vp = g_vp[r * 256 + d];
            par += vp * cp; pai += vp * sp;
        }
    }
    int base = blk * 64 * 256;
    #pragma unroll
    for (int f = 0; f < 64; f++) g_Spart[base + f * 256 + d] = acc[f];
    int s = c * 4 + t;
    g_psum[(b * 64 + s) * 512 + d] = par;
    g_psum[(b * 64 + s) * 512 + 256 + d] = pai;
}

// ================= Kernel 4: exclusive prefixes (front-batched loads) =================
__global__ __launch_bounds__(256) void k4_prefix()
{
    int tid = threadIdx.x;
    if (blockIdx.x < 128) {
        int idx = blockIdx.x * 256 + tid;       // (b, f*256+d) -> 32768 chains
        int b = idx >> 14, rd = idx & 16383;
        float v[64];
        #pragma unroll
        for (int c = 0; c < 16; c++)
            #pragma unroll
            for (int t = 0; t < 4; t++)
                v[c*4+t] = g_Spart[(((b * 16 + c) * 4) + t) * 16384 + rd];
        float run = 0.f;
        #pragma unroll
        for (int c = 0; c < 16; c++) {
            g_P[(b * 16 + c) * 16384 + rd] = run;
            run += (v[c*4] + v[c*4+1]) + (v[c*4+2] + v[c*4+3]);
        }
    } else {
        int e = (blockIdx.x - 128) * 256 + tid;
        if (e < 1024) {
            int b = e >> 9, rd = e & 511;
            float v[64];
            #pragma unroll
            for (int s = 0; s < 64; s++) v[s] = g_psum[(b * 64 + s) * 512 + rd];
            float run = 0.f;
            #pragma unroll
            for (int s = 0; s < 64; s++) {
                g_pprefix[(b * 64 + s) * 512 + rd] = run;
                run += v[s];
            }
        }
    }
}

// ================= Kernel 5: intra-chunk masked scores (tf32 mma) =================
__global__ __launch_bounds__(256) void k5_mma()
{
    __shared__ float As[2][128][20];
    __shared__ float Bs[2][16][132];
    int bc = blockIdx.x; int b = bc >> 4, c = bc & 15;
    int row0 = b * LL + c * CC;
    int tid = threadIdx.x;
    int w = tid >> 5, lane = tid & 31;
    int wm = (w & 3) * 32;
    int wn = (w >> 2) * 64;
    int lq = lane >> 2, lr = lane & 3;
    int r0 = tid >> 2, c4 = (tid & 3) * 4;
    float acc[2][8][4] = {};
    float4 a0v, a1v, u0, u1;

    a0v = *(const float4*)&g_qf[(row0 + r0) * 64 + c4];
    a1v = *(const float4*)&g_qf[(row0 + r0 + 64) * 64 + c4];
    u0  = *(const float4*)&g_kf[(row0 + r0) * 64 + c4];
    u1  = *(const float4*)&g_kf[(row0 + r0 + 64) * 64 + c4];
    {
        As[0][r0][c4+0]=f2tf32f(a0v.x); As[0][r0][c4+1]=f2tf32f(a0v.y);
        As[0][r0][c4+2]=f2tf32f(a0v.z); As[0][r0][c4+3]=f2tf32f(a0v.w);
        As[0][r0+64][c4+0]=f2tf32f(a1v.x); As[0][r0+64][c4+1]=f2tf32f(a1v.y);
        As[0][r0+64][c4+2]=f2tf32f(a1v.z); As[0][r0+64][c4+3]=f2tf32f(a1v.w);
        Bs[0][c4+0][r0]=f2tf32f(u0.x); Bs[0][c4+1][r0]=f2tf32f(u0.y);
        Bs[0][c4+2][r0]=f2tf32f(u0.z); Bs[0][c4+3][r0]=f2tf32f(u0.w);
        Bs[0][c4+0][r0+64]=f2tf32f(u1.x); Bs[0][c4+1][r0+64]=f2tf32f(u1.y);
        Bs[0][c4+2][r0+64]=f2tf32f(u1.z); Bs[0][c4+3][r0+64]=f2tf32f(u1.w);
    }
    __syncthreads();

    for (int s = 0; s < 4; s++) {
        int cur = s & 1;
        if (s < 3) {
            int kn = (s + 1) * 16;
            a0v = *(const float4*)&g_qf[(row0 + r0) * 64 + kn + c4];
            a1v = *(const float4*)&g_qf[(row0 + r0 + 64) * 64 + kn + c4];
            u0  = *(const float4*)&g_kf[(row0 + r0) * 64 + kn + c4];
            u1  = *(const float4*)&g_kf[(row0 + r0 + 64) * 64 + kn + c4];
        }
        #pragma unroll
        for (int ks = 0; ks < 2; ks++) {
            unsigned a[2][4];
            #pragma unroll
            for (int mt = 0; mt < 2; mt++) {
                int rr = wm + mt*16 + lq;
                int cc = ks*8 + lr;
                a[mt][0] = __float_as_uint(As[cur][rr][cc]);
                a[mt][1] = __float_as_uint(As[cur][rr+8][cc]);
                a[mt][2] = __float_as_uint(As[cur][rr][cc+4]);
                a[mt][3] = __float_as_uint(As[cur][rr+8][cc+4]);
            }
            #pragma unroll
            for (int nt = 0; nt < 8; nt++) {
                int bn = wn + nt*8 + lq;
                unsigned b0 = __float_as_uint(Bs[cur][ks*8+lr][bn]);
                unsigned b1 = __float_as_uint(Bs[cur][ks*8+lr+4][bn]);
                #pragma unroll
                for (int mt = 0; mt < 2; mt++)
                    mma_tf32(acc[mt][nt], a[mt][0], a[mt][1], a[mt][2], a[mt][3], b0, b1);
            }
        }
        if (s < 3) {
            int nb = cur ^ 1;
            As[nb][r0][c4+0]=f2tf32f(a0v.x); As[nb][r0][c4+1]=f2tf32f(a0v.y);
            As[nb][r0][c4+2]=f2tf32f(a0v.z); As[nb][r0][c4+3]=f2tf32f(a0v.w);
            As[nb][r0+64][c4+0]=f2tf32f(a1v.x); As[nb][r0+64][c4+1]=f2tf32f(a1v.y);
            As[nb][r0+64][c4+2]=f2tf32f(a1v.z); As[nb][r0+64][c4+3]=f2tf32f(a1v.w);
            Bs[nb][c4+0][r0]=f2tf32f(u0.x); Bs[nb][c4+1][r0]=f2tf32f(u0.y);
            Bs[nb][c4+2][r0]=f2tf32f(u0.z); Bs[nb][c4+3][r0]=f2tf32f(u0.w);
            Bs[nb][c4+0][r0+64]=f2tf32f(u1.x); Bs[nb][c4+1][r0+64]=f2tf32f(u1.y);
            Bs[nb][c4+2][r0+64]=f2tf32f(u1.z); Bs[nb][c4+3][r0+64]=f2tf32f(u1.w);
        }
        __syncthreads();
    }
    int sb = bc * CC * CC;
    #pragma unroll
    for (int mt = 0; mt < 2; mt++) {
        #pragma unroll
        for (int nt = 0; nt < 8; nt++) {
            int la = wm + mt*16 + lq;
            int lb = la + 8;
            int j0 = wn + nt*8 + lr*2;
            int j1 = j0 + 1;
            *(float2*)&g_scores[sb + la*128 + j0] =
                make_float2(j0 <= la ? acc[mt][nt][0] : 0.f, j1 <= la ? acc[mt][nt][1] : 0.f);
            *(float2*)&g_scores[sb + lb*128 + j0] =
                make_float2(j0 <= lb ? acc[mt][nt][2] : 0.f, j1 <= lb ? acc[mt][nt][3] : 0.f);
        }
    }
}

// ================= Kernel 6: content output (tf32 mma): [qf | scores] @ [P ; vc] ======
__global__ __launch_bounds__(256) void k6_mma()
{
    __shared__ float As[2][128][20];
    __shared__ float Bs[2][16][68];
    int bc = blockIdx.x; int b = bc >> 4, c = bc & 15;
    int d0 = blockIdx.y * 64;
    int row0 = b * LL + c * CC;
    int tid = threadIdx.x;
    int w = tid >> 5, lane = tid & 31;
    int wm = (w & 3) * 32;
    int wn = (w >> 2) * 32;
    int lq = lane >> 2, lr = lane & 3;
    int r0 = tid >> 2, c4 = (tid & 3) * 4;
    int br = tid >> 4, bc4 = (tid & 15) * 4;
    int Pbase = bc * 64 * 256;
    int sbase = bc * CC * CC;
    float acc[2][4][4] = {};
    float4 a0v, a1v, bv;

    // stage 0: kg = c4 in [0,16) -> qf ; br in [0,16) -> P
    a0v = *(const float4*)&g_qf[(row0 + r0) * 64 + c4];
    a1v = *(const float4*)&g_qf[(row0 + r0 + 64) * 64 + c4];
    bv  = *(const float4*)&g_P[Pbase + br * 256 + d0 + bc4];
    {
        As[0][r0][c4+0]=f2tf32f(a0v.x); As[0][r0][c4+1]=f2tf32f(a0v.y);
        As[0][r0][c4+2]=f2tf32f(a0v.z); As[0][r0][c4+3]=f2tf32f(a0v.w);
        As[0][r0+64][c4+0]=f2tf32f(a1v.x); As[0][r0+64][c4+1]=f2tf32f(a1v.y);
        As[0][r0+64][c4+2]=f2tf32f(a1v.z); As[0][r0+64][c4+3]=f2tf32f(a1v.w);
        Bs[0][br][bc4+0]=f2tf32f(bv.x); Bs[0][br][bc4+1]=f2tf32f(bv.y);
        Bs[0][br][bc4+2]=f2tf32f(bv.z); Bs[0][br][bc4+3]=f2tf32f(bv.w);
    }
    __syncthreads();

    for (int s = 0; s < 12; s++) {
        int cur = s & 1;
        if (s < 11) {
            int kn = (s + 1) * 16;
            int kga = kn + c4;
            if (kga < 64) {
                a0v = *(const float4*)&g_qf[(row0 + r0) * 64 + kga];
                a1v = *(const float4*)&g_qf[(row0 + r0 + 64) * 64 + kga];
            } else {
                a0v = *(const float4*)&g_scores[sbase + r0 * 128 + kga - 64];
                a1v = *(const float4*)&g_scores[sbase + (r0 + 64) * 128 + kga - 64];
            }
            int kgb = kn + br;
            if (kgb < 64) bv = *(const float4*)&g_P[Pbase + kgb * 256 + d0 + bc4];
            else          bv = *(const float4*)&g_vc[(row0 + kgb - 64) * 256 + d0 + bc4];
        }
        #pragma unroll
        for (int ks = 0; ks < 2; ks++) {
            unsigned a[2][4];
            #pragma unroll
            for (int mt = 0; mt < 2; mt++) {
                int rr = wm + mt*16 + lq;
                int cc = ks*8 + lr;
                a[mt][0] = __float_as_uint(As[cur][rr][cc]);
                a[mt][1] = __float_as_uint(As[cur][rr+8][cc]);
                a[mt][2] = __float_as_uint(As[cur][rr][cc+4]);
                a[mt][3] = __float_as_uint(As[cur][rr+8][cc+4]);
            }
            #pragma unroll
            for (int nt = 0; nt < 4; nt++) {
                int bn = wn + nt*8 + lq;
                unsigned b0 = __float_as_uint(Bs[cur][ks*8+lr][bn]);
                unsigned b1 = __float_as_uint(Bs[cur][ks*8+lr+4][bn]);
                #pragma unroll
                for (int mt = 0; mt < 2; mt++)
                    mma_tf32(acc[mt][nt], a[mt][0], a[mt][1], a[mt][2], a[mt][3], b0, b1);
            }
        }
        if (s < 11) {
            int nb = cur ^ 1;
            As[nb][r0][c4+0]=f2tf32f(a0v.x); As[nb][r0][c4+1]=f2tf32f(a0v.y);
            As[nb][r0][c4+2]=f2tf32f(a0v.z); As[nb][r0][c4+3]=f2tf32f(a0v.w);
            As[nb][r0+64][c4+0]=f2tf32f(a1v.x); As[nb][r0+64][c4+1]=f2tf32f(a1v.y);
            As[nb][r0+64][c4+2]=f2tf32f(a1v.z); As[nb][r0+64][c4+3]=f2tf32f(a1v.w);
            Bs[nb][br][bc4+0]=f2tf32f(bv.x); Bs[nb][br][bc4+1]=f2tf32f(bv.y);
            Bs[nb][br][bc4+2]=f2tf32f(bv.z); Bs[nb][br][bc4+3]=f2tf32f(bv.w);
        }
        __syncthreads();
    }
    #pragma unroll
    for (int mt = 0; mt < 2; mt++) {
        #pragma unroll
        for (int nt = 0; nt < 4; nt++) {
            int la = wm + mt*16 + lq;
            int lb = la + 8;
            int cc = d0 + wn + nt*8 + lr*2;
            float sa = rsqrtf((float)((c*CC + la + 1) * KK));
            float sb2 = rsqrtf((float)((c*CC + lb + 1) * KK));
            *(float2*)&g_cont[(row0 + la) * 256 + cc] =
                make_float2(acc[mt][nt][0] * sa, acc[mt][nt][1] * sa);
            *(float2*)&g_cont[(row0 + lb) * 256 + cc] =
                make_float2(acc[mt][nt][2] * sb2, acc[mt][nt][3] * sb2);
        }
    }
}

// ================= Kernel 7: pos scan (32 rows/block) + gate combine + LayerNorm =================
__global__ __launch_bounds__(256) void k7_poscomb(
    const float* __restrict__ base_phases,
    const float* __restrict__ ln_g, const float* __restrict__ ln_b)
{
    __shared__ float comb[32][257];
    int blk = blockIdx.x;           // (b*16+c)*4 + t
    int bc = blk >> 2, t = blk & 3;
    int b = bc >> 4, c = bc & 15;
    int row0 = b * LL + c * CC + t * 32;
    int l0 = c * CC + t * 32;
    int d = threadIdx.x;
    int s = c * 4 + t;
    float ar = g_pprefix[(b * 64 + s) * 512 + d];
    float ai = g_pprefix[(b * 64 + s) * 512 + 256 + d];
    int w = d >> 5, lane = d & 31;
    for (int lt = 0; lt < 32; lt++) {
        int l = l0 + lt;
        int r = row0 + lt;
        float ph = base_phases[l*256 + d];
        float sp, cp; __sincosf(ph, &sp, &cp);
        float v = g_vp[r*256 + d];
        ar += v * cp; ai += v * sp;
        float pret = (ar*cp + ai*sp) * rsqrtf((float)(l + 1));
        float g0 = g_gates[r*2], g1v = g_gates[r*2+1];
        float cv = g_cont[r*256 + d];
        comb[lt][d] = g0 * pret + g1v * cv;
    }
    __syncthreads();
    #pragma unroll
    for (int q = 0; q < 4; q++) {
        int lt = w*4 + q;
        int r = row0 + lt;
        float vals[8]; float s1 = 0.f, s2 = 0.f;
        #pragma unroll
        for (int k = 0; k < 8; k++) {
            float v = comb[lt][lane + 32*k];
            vals[k] = v; s1 += v; s2 += v*v;
        }
        #pragma unroll
        for (int off = 16; off; off >>= 1) {
            s1 += __shfl_xor_sync(~0u, s1, off);
            s2 += __shfl_xor_sync(~0u, s2, off);
        }
        float mu = s1 * (1.f/256.f);
        float var = s2 * (1.f/256.f) - mu*mu;
        float rstd = rsqrtf(var + 1e-5f);
        #pragma unroll
        for (int k = 0; k < 8; k++) {
            int dd = lane + 32*k;
            g_norm[r*256 + dd] = (vals[k] - mu) * rstd * ln_g[dd] + ln_b[dd];
        }
    }
}

// ================= Kernel 8: out = x + normed @ Wo + bo (tf32 mma, double-buffered) ==
__global__ __launch_bounds__(256) void k8_mma(
    const float* __restrict__ x, const float* __restrict__ Wo,
    const float* __restrict__ bo, float* __restrict__ out)
{
    __shared__ float As[2][128][20];
    __shared__ float Bs[2][16][68];
    int row0 = blockIdx.x * 128;
    int colbase = blockIdx.y * 64;
    int tid = threadIdx.x;
    int w = tid >> 5, lane = tid & 31;
    int wm = (w & 3) * 32;
    int wn = (w >> 2) * 32;
    int lq = lane >> 2, lr = lane & 3;
    int r0 = tid >> 2, c4 = (tid & 3) * 4;
    int br = tid >> 4, bc4 = (tid & 15) * 4;
    float c[2][4][4] = {};
    float4 av0, av1, bv;

    av0 = *(const float4*)&g_norm[(row0 + r0) * 256 + c4];
    av1 = *(const float4*)&g_norm[(row0 + r0 + 64) * 256 + c4];
    bv  = *(const float4*)&Wo[br * 256 + colbase + bc4];
    As[0][r0][c4+0]=f2tf32f(av0.x); As[0][r0][c4+1]=f2tf32f(av0.y);
    As[0][r0][c4+2]=f2tf32f(av0.z); As[0][r0][c4+3]=f2tf32f(av0.w);
    As[0][r0+64][c4+0]=f2tf32f(av1.x); As[0][r0+64][c4+1]=f2tf32f(av1.y);
    As[0][r0+64][c4+2]=f2tf32f(av1.z); As[0][r0+64][c4+3]=f2tf32f(av1.w);
    Bs[0][br][bc4+0]=f2tf32f(bv.x); Bs[0][br][bc4+1]=f2tf32f(bv.y);
    Bs[0][br][bc4+2]=f2tf32f(bv.z); Bs[0][br][bc4+3]=f2tf32f(bv.w);
    __syncthreads();

    for (int s = 0; s < 16; s++) {
        int cur = s & 1;
        if (s < 15) {
            int kn = (s + 1) * 16;
            av0 = *(const float4*)&g_norm[(row0 + r0) * 256 + kn + c4];
            av1 = *(const float4*)&g_norm[(row0 + r0 + 64) * 256 + kn + c4];
            bv  = *(const float4*)&Wo[(kn + br) * 256 + colbase + bc4];
        }
        #pragma unroll
        for (int ks = 0; ks < 2; ks++) {
            unsigned a[2][4];
            #pragma unroll
            for (int mt = 0; mt < 2; mt++) {
                int rr = wm + mt*16 + lq;
                int cc = ks*8 + lr;
                a[mt][0] = __float_as_uint(As[cur][rr][cc]);
                a[mt][1] = __float_as_uint(As[cur][rr+8][cc]);
                a[mt][2] = __float_as_uint(As[cur][rr][cc+4]);
                a[mt][3] = __float_as_uint(As[cur][rr+8][cc+4]);
            }
            #pragma unroll
            for (int nt = 0; nt < 4; nt++) {
                int bn = wn + nt*8 + lq;
                unsigned b0 = __float_as_uint(Bs[cur][ks*8+lr][bn]);
                unsigned b1 = __float_as_uint(Bs[cur][ks*8+lr+4][bn]);
                #pragma unroll
                for (int mt = 0; mt < 2; mt++)
                    mma_tf32(c[mt][nt], a[mt][0], a[mt][1], a[mt][2], a[mt][3], b0, b1);
            }
        }
        if (s < 15) {
            int nb = cur ^ 1;
            As[nb][r0][c4+0]=f2tf32f(av0.x); As[nb][r0][c4+1]=f2tf32f(av0.y);
            As[nb][r0][c4+2]=f2tf32f(av0.z); As[nb][r0][c4+3]=f2tf32f(av0.w);
            As[nb][r0+64][c4+0]=f2tf32f(av1.x); As[nb][r0+64][c4+1]=f2tf32f(av1.y);
            As[nb][r0+64][c4+2]=f2tf32f(av1.z); As[nb][r0+64][c4+3]=f2tf32f(av1.w);
            Bs[nb][br][bc4+0]=f2tf32f(bv.x); Bs[nb][br][bc4+1]=f2tf32f(bv.y);
            Bs[nb][br][bc4+2]=f2tf32f(bv.z); Bs[nb][br][bc4+3]=f2tf32f(bv.w);
        }
        __syncthreads();
    }
    #pragma unroll
    for (int mt = 0; mt < 2; mt++) {
        #pragma unroll
        for (int nt = 0; nt < 4; nt++) {
            int r = row0 + wm + mt*16 + lq;
            int cc = colbase + wn + nt*8 + lr*2;
            float b0v = bo[cc], b1v = bo[cc+1];
            float2 x0 = *(const float2*)&x[r * 256 + cc];
            float2 x1 = *(const float2*)&x[(r+8) * 256 + cc];
            *(float2*)&out[r * 256 + cc] =
                make_float2(c[mt][nt][0] + b0v + x0.x, c[mt][nt][1] + b1v + x0.y);
            *(float2*)&out[(r+8) * 256 + cc] =
                make_float2(c[mt][nt][2] + b0v + x1.x, c[mt][nt][3] + b1v + x1.y);
        }
    }
}

// ================= launcher =================
extern "C" void kernel_launch(void* const* d_in, const int* in_sizes, int n_in,
                              void* d_out, int out_size)
{
    const float* x   = (const float*)d_in[0];
    const float* bp  = (const float*)d_in[1];
    const float* Wk1 = (const float*)d_in[2];
    const float* bk1 = (const float*)d_in[3];
    const float* Wk2 = (const float*)d_in[4];
    const float* bk2 = (const float*)d_in[5];
    const float* Wq1 = (const float*)d_in[6];
    const float* bq1 = (const float*)d_in[7];
    const float* Wq2 = (const float*)d_in[8];
    const float* bq2 = (const float*)d_in[9];
    const float* Wvc = (const float*)d_in[10];
    const float* bvc = (const float*)d_in[11];
    const float* Wvp = (const float*)d_in[12];
    const float* bvp = (const float*)d_in[13];
    const float* Wg1 = (const float*)d_in[14];
    const float* bg1 = (const float*)d_in[15];
    const float* Wg2 = (const float*)d_in[16];
    const float* bg2 = (const float*)d_in[17];
    const float* lng = (const float*)d_in[18];
    const float* lnb = (const float*)d_in[19];
    const float* Wo  = (const float*)d_in[20];
    const float* bo  = (const float*)d_in[21];
    float* out = (float*)d_out;

    k1_mma<<<dim3(32, 17), 256>>>(x, Wk1, bk1, Wq1, bq1, Wvc, bvc, Wvp, bvp, Wg1, bg1);
    k2_mma<<<32, 256>>>(Wk2, bk2, Wq2, bq2, Wg2, bg2);
    k3_chunksum<<<128, 256>>>(bp);
    k4_prefix<<<132, 256>>>();
    k5_mma<<<32, 256>>>();
    k6_mma<<<dim3(32, 4), 256>>>();
    k7_poscomb<<<128, 256>>>(bp, lng, lnb);
    k8_mma<<<dim3(32, 4), 256>>>(x, Wo, bo, out);
}